// round 12
// baseline (speedup 1.0000x reference)
#include <cuda_runtime.h>

// Shapes (fixed): h=8, n=8, d=512, c=64, c2=32, i=96, kk=3
// Output layout: [ T (8*64*96*96) | M (8*8*32) | P (8*8*64*96*96) | w (same as P) ]
#define T_OFF   0
#define M_OFF   4718592
#define P_OFF   4720640
#define W_OFF   42469376
#define INV24   (1.0f/24.0f)

// ---------------- scratch (device globals; no allocation) ----------------
__device__ __align__(16) float g_M[2048];                       // [n][h][32]
__device__ __align__(16) float g_Ak[4096],  g_Av[4096];         // [n][h][64]
__device__ __align__(16) float g_Bxk[49152], g_Byk[49152];      // [h][64][96]
__device__ __align__(16) float g_Bxv[49152], g_Byv[49152];      // [h][64][96]
__device__ __align__(16) float g_swX[36864], g_swY[36864];      // [slab][cin][o]  (TRANSPOSED)
__device__ __align__(16) float g_U[36864];                      // [n][h][o][xc][ky]
__device__ __align__(16) float g_Vx[442368], g_Vy[442368];      // [h][o][slab][96]
__device__ __align__(16) float g_EX[147456];                    // [h][o][yc][96]
__device__ __align__(16) float g_EY[1179648];                   // [n][h][o][xc][96]
__device__ __align__(16) float g_VY[393216];                    // [n][h][o][96]

// ---- K1 (fused): per-head [embed -> axes -> btab] (b<8) | swtab (8..15) ----
__global__ void k_setup(const float* __restrict__ X, const float* __restrict__ lw,
                        const float* __restrict__ lb, const float* __restrict__ gam,
                        const float* __restrict__ bet,
                        const float* __restrict__ kw, const float* __restrict__ kb,
                        const float* __restrict__ vw, const float* __restrict__ vb,
                        const float* __restrict__ px, const float* __restrict__ py,
                        const float* __restrict__ sw, float* __restrict__ outM) {
    int b = blockIdx.x, t = threadIdx.x;
    if (b >= 8) {
        // ---- swtab: border-class conv weight tables, TRANSPOSED [slab][cin][o] ----
        #pragma unroll
        for (int k = 0; k < 2; k++) {
            int tt = (b - 8) * 512 + k * 256 + t;   // tt = o*64 + cin
            int o = tt >> 6, cin = tt & 63;
            int tr = cin * 64 + o;
            float s[3][3];
            const float* p = sw + tt * 9;
            #pragma unroll
            for (int ky = 0; ky < 3; ky++)
                #pragma unroll
                for (int kx = 0; kx < 3; kx++) s[ky][kx] = p[ky * 3 + kx];
            #pragma unroll
            for (int xc = 0; xc < 3; xc++)
                #pragma unroll
                for (int ky = 0; ky < 3; ky++) {
                    float v = (xc == 0) ? (s[ky][1] + s[ky][2])
                            : (xc == 1) ? (s[ky][0] + s[ky][1] + s[ky][2])
                                        : (s[ky][0] + s[ky][1]);
                    g_swX[(xc * 3 + ky) * 4096 + tr] = v;
                }
            #pragma unroll
            for (int yc = 0; yc < 3; yc++)
                #pragma unroll
                for (int kx = 0; kx < 3; kx++) {
                    float v = (yc == 0) ? (s[1][kx] + s[2][kx])
                            : (yc == 1) ? (s[0][kx] + s[1][kx] + s[2][kx])
                                        : (s[0][kx] + s[1][kx]);
                    g_swY[(yc * 3 + kx) * 4096 + tr] = v;
                }
        }
        return;
    }
    int h = b;
    __shared__ float Xs[4096];
    __shared__ float Ws[32 * 129];   // padded (stride 129 -> conflict-free)
    __shared__ float ys[256];
    __shared__ float Ms[256];        // M[n][c] for this head
    __shared__ float mu_s[32], iv_s[32];
    const float* Xh = X + h * 4096;
    for (int k = t; k < 4096; k += 256) Xs[k] = Xh[k];

    // ---- linear: smem-tiled GEMV, all global loads coalesced ----
    int nn = t >> 5, cc = t & 31;
    float acc = 0.f;
    #pragma unroll
    for (int tile = 0; tile < 4; tile++) {
        __syncthreads();
        for (int k = t; k < 4096; k += 256) {
            int row = k >> 7, dd = k & 127;
            Ws[row * 129 + dd] = lw[(h * 32 + row) * 512 + tile * 128 + dd];
        }
        __syncthreads();
        const float* xp = Xs + nn * 512 + tile * 128;
        const float* wp = Ws + cc * 129;
        #pragma unroll 8
        for (int dd = 0; dd < 128; dd++) acc += xp[dd] * wp[dd];
    }
    acc += lb[h * 32 + cc];
    ys[t] = acc;
    __syncthreads();
    if (t < 32) {
        float m = 0.f;
        for (int j = 0; j < 8; j++) m += ys[j * 32 + t];
        m *= 0.125f;
        float v = 0.f;
        for (int j = 0; j < 8; j++) { float d0 = ys[j * 32 + t] - m; v += d0 * d0; }
        v *= 0.125f;
        mu_s[t] = m;
        iv_s[t] = rsqrtf(v + 1e-5f);
    }
    __syncthreads();
    float val = (acc - mu_s[cc]) * iv_s[cc] * gam[h * 32 + cc] + bet[h * 32 + cc];
    val = fmaxf(val, 0.f);
    Ms[t] = val;
    int midx = (nn * 8 + h) * 32 + cc;
    g_M[midx]  = val;
    outM[midx] = val;
    __syncthreads();

    // ---- axes: A_k/A_v (512 items: n x d) ----
    for (int k = t; k < 512; k += 256) {
        int d = k & 63, n2 = k >> 6;
        const float* kwr = kw + (h * 64 + d) * 64;
        const float* vwr = vw + (h * 64 + d) * 64;
        const float* Mr  = Ms + n2 * 32;
        float ak = 0.f, av = 0.f;
        #pragma unroll 8
        for (int c = 0; c < 32; c++) {
            float m = Mr[c];
            ak += (kwr[c] + kwr[c + 32]) * m;
            av += (vwr[c] + vwr[c + 32]) * m;
        }
        g_Ak[(n2 * 8 + h) * 64 + d] = ak + kb[h * 64 + d];
        g_Av[(n2 * 8 + h) * 64 + d] = av + vb[h * 64 + d];
    }

    // ---- btab: Bx/By tables (6144 items: d x pos) ----
    for (int k = t; k < 6144; k += 256) {
        int pos = k % 96, d = k / 96;
        const float* kwr = kw + (h * 64 + d) * 64;
        const float* vwr = vw + (h * 64 + d) * 64;
        float bxk = 0.f, byk = 0.f, bxv = 0.f, byv = 0.f;
        #pragma unroll 8
        for (int c = 0; c < 32; c++) {
            float pxv = px[c * 96 + pos];
            float pyv = py[c * 96 + pos];
            bxk += kwr[c]      * pxv;
            byk += kwr[c + 32] * pyv;
            bxv += vwr[c]      * pxv;
            byv += vwr[c + 32] * pyv;
        }
        int idx = (h * 64 + d) * 96 + pos;
        g_Bxk[idx] = bxk; g_Byk[idx] = byk; g_Bxv[idx] = bxv; g_Byv[idx] = byv;
    }
}

// --- K2 (fused): u (b<16) | Vy (16..63) | Vx (64..111), register-blocked ----
__global__ void k_tab2() {
    int b = blockIdx.x, tid = threadIdx.x;
    if (b < 16) {
        // ---- U[n,h,o,s] = sum_c swX[s,c,o] * Ak[n,h,c]  (coalesced over o) ----
        int t = b * 256 + tid;
        int o = t & 63, h = (t >> 6) & 7, n = t >> 9;
        const float* ap = g_Ak + (n * 8 + h) * 64;
        float acc[9] = {0,0,0,0,0,0,0,0,0};
        for (int c = 0; c < 64; c++) {
            float a = ap[c];
            #pragma unroll
            for (int s = 0; s < 9; s++)
                acc[s] += g_swX[s * 4096 + c * 64 + o] * a;
        }
        int base = ((n * 8 + h) * 64 + o) * 9;
        #pragma unroll
        for (int s = 0; s < 9; s++) g_U[base + s] = acc[s];
    } else if (b < 64) {
        // ---- Vy[h,o,s,pos] = sum_c swX[s,c,o] * Byk[h,c,pos], float4 pos ----
        int t = (b - 16) * 256 + tid;          // 0..12287
        int q = t % 24; int r = t / 24;
        int o = r & 63, h = r >> 6;
        const float4* byp = (const float4*)(g_Byk + h * 6144) + q;
        float4 acc[9];
        #pragma unroll
        for (int s = 0; s < 9; s++) acc[s] = make_float4(0.f, 0.f, 0.f, 0.f);
        for (int c = 0; c < 64; c++) {
            float4 by = byp[c * 24];
            #pragma unroll
            for (int s = 0; s < 9; s++) {
                float w = g_swX[s * 4096 + c * 64 + o];
                acc[s].x += w * by.x; acc[s].y += w * by.y;
                acc[s].z += w * by.z; acc[s].w += w * by.w;
            }
        }
        #pragma unroll
        for (int s = 0; s < 9; s++)
            *(float4*)(g_Vy + ((h * 64 + o) * 9 + s) * 96 + q * 4) = acc[s];
    } else {
        // ---- Vx[h,o,s,pos] = sum_c swY[s,c,o] * Bxk[h,c,pos] ----
        int t = (b - 64) * 256 + tid;
        int q = t % 24; int r = t / 24;
        int o = r & 63, h = r >> 6;
        const float4* bxp = (const float4*)(g_Bxk + h * 6144) + q;
        float4 acc[9];
        #pragma unroll
        for (int s = 0; s < 9; s++) acc[s] = make_float4(0.f, 0.f, 0.f, 0.f);
        for (int c = 0; c < 64; c++) {
            float4 bx = bxp[c * 24];
            #pragma unroll
            for (int s = 0; s < 9; s++) {
                float w = g_swY[s * 4096 + c * 64 + o];
                acc[s].x += w * bx.x; acc[s].y += w * bx.y;
                acc[s].z += w * bx.z; acc[s].w += w * bx.w;
            }
        }
        #pragma unroll
        for (int s = 0; s < 9; s++)
            *(float4*)(g_Vx + ((h * 64 + o) * 9 + s) * 96 + q * 4) = acc[s];
    }
}

// --------- K3 (fused): ex (b<576) | ey (576..5183) | vy4 (5184..5567) ------
__global__ void k_tab3(const float* __restrict__ sb) {
    int b = blockIdx.x, tid = threadIdx.x;
    if (b < 576) {
        int t = b * 256 + tid;
        int jj = t % 96; int r = t / 96;
        int yc = r % 3;  r /= 3;
        int o = r % 64;  int h = r / 64;
        int base = ((h * 64 + o) * 3 + yc) * 3 * 96;
        float acc = 0.f;
        #pragma unroll
        for (int kx = 0; kx < 3; kx++) {
            int j2 = jj + kx - 1;
            if (j2 >= 0 && j2 < 96) acc += g_Vx[base + kx * 96 + j2];
        }
        g_EX[t] = expf(acc * INV24);
    } else if (b < 5184) {
        int t = (b - 576) * 256 + tid;
        int ii = t % 96; int r = t / 96;
        int xc = r % 3;  r /= 3;
        int o = r % 64;  r /= 64;
        int h = r % 8;   int n = r / 8;
        int ub = (((n * 8 + h) * 64 + o) * 3 + xc) * 3;
        int vb = ((h * 64 + o) * 3 + xc) * 3 * 96;
        float acc = sb[o];
        #pragma unroll
        for (int ky = 0; ky < 3; ky++) {
            int i2 = ii + ky - 1;
            if (i2 >= 0 && i2 < 96) acc += g_U[ub + ky] + g_Vy[vb + ky * 96 + i2];
        }
        g_EY[t] = expf(acc * INV24);
    } else {
        int t = (b - 5184) * 256 + tid;
        int q = t % 24; int r = t / 24;
        int o = r % 64;  r /= 64;
        int h = r % 8;   int n = r / 8;
        float av = g_Av[(n * 8 + h) * 64 + o];
        float4 by = *(const float4*)(g_Byv + (h * 64 + o) * 96 + q * 4);
        float4 vout = {av + by.x, av + by.y, av + by.z, av + by.w};
        *(float4*)(g_VY + ((n * 8 + h) * 64 + o) * 96 + q * 4) = vout;
    }
}

// -------- K4: main — two-pass, low-register, float4 stores (T, w, P) -------
__global__ void __launch_bounds__(384, 3) k_main(const float* __restrict__ px,
                                                 const float* __restrict__ py,
                                                 float* __restrict__ out) {
    int jq  = threadIdx.x;                           // 0..23 -> 4 jj each
    int jj0 = jq * 4;
    int ii  = blockIdx.x * 16 + threadIdx.y;         // 0..95
    int o   = blockIdx.y;                            // 0..63
    int n   = blockIdx.z;                            // 0..7
    int yc  = (ii == 0) ? 0 : ((ii == 95) ? 2 : 1);
    int off0 = (jq == 0)  ? 0   : 96;                // xc offset for lane-element 0
    int off3 = (jq == 23) ? 192 : 96;                // xc offset for lane-element 3

    int eyB = (n * 512 + o) * 288 + ii;              // + h*18432 (+off)
    int exB = (o * 3 + yc) * 96 + jj0;               // + h*18432
    int vyB = (n * 512 + o) * 96 + ii;               // + h*6144
    int bxB = o * 96 + jj0;                          // + h*6144

    float s0 = 0.f, s1 = 0.f, s2 = 0.f, s3 = 0.f;
    float a0 = 0.f, a1 = 0.f, a2 = 0.f, a3 = 0.f;
    #pragma unroll
    for (int h = 0; h < 8; h++) {
        const float* ey = g_EY + eyB + h * 18432;
        float eyM = ey[96], ey0 = ey[off0], ey3 = ey[off3];
        float4 ex = *(const float4*)(g_EX + exB + h * 18432);
        float  vy = g_VY[vyB + h * 6144];
        float4 bx = *(const float4*)(g_Bxv + bxB + h * 6144);
        float e0 = ey0 * ex.x, e1 = eyM * ex.y, e2 = eyM * ex.z, e3 = ey3 * ex.w;
        s0 += e0; s1 += e1; s2 += e2; s3 += e3;
        a0 += e0 * (vy + bx.x); a1 += e1 * (vy + bx.y);
        a2 += e2 * (vy + bx.z); a3 += e3 * (vy + bx.w);
    }
    float i0 = __fdividef(1.f, s0), i1 = __fdividef(1.f, s1);
    float i2 = __fdividef(1.f, s2), i3 = __fdividef(1.f, s3);

    int p0 = ii * 96 + jj0;
    float4 t4 = {a0 * i0, a1 * i1, a2 * i2, a3 * i3};
    __stcs((float4*)(out + T_OFF + (n * 64 + o) * 9216 + p0), t4);

    float4 pAdd;
    if (o < 32) {
        pAdd = *(const float4*)(px + o * 96 + jj0);
    } else {
        float v = py[(o - 32) * 96 + ii];
        pAdd = make_float4(v, v, v, v);
    }
    int wB = W_OFF + (n * 512 + o) * 9216 + p0;      // + h*589824
    int pB = P_OFF + (n * 512 + o) * 9216 + p0;
    int mB = n * 256 + (o & 31);                     // + h*32

    #pragma unroll
    for (int h = 0; h < 8; h++) {
        const float* ey = g_EY + eyB + h * 18432;
        float eyM = ey[96], ey0 = ey[off0], ey3 = ey[off3];
        float4 ex = *(const float4*)(g_EX + exB + h * 18432);
        float4 w4 = {ey0 * ex.x * i0, eyM * ex.y * i1,
                     eyM * ex.z * i2, ey3 * ex.w * i3};
        __stcs((float4*)(out + wB + h * 589824), w4);
        float m = g_M[mB + h * 32];
        float4 p4 = {m + pAdd.x, m + pAdd.y, m + pAdd.z, m + pAdd.w};
        __stcs((float4*)(out + pB + h * 589824), p4);
    }
}

// ---------------- launch ----------------------------------------------------
extern "C" void kernel_launch(void* const* d_in, const int* in_sizes, int n_in,
                              void* d_out, int out_size) {
    const float* X     = (const float*)d_in[0];
    const float* lin_w = (const float*)d_in[1];
    const float* lin_b = (const float*)d_in[2];
    const float* gam   = (const float*)d_in[3];
    const float* bet   = (const float*)d_in[4];
    const float* px    = (const float*)d_in[5];
    const float* py    = (const float*)d_in[6];
    const float* kw    = (const float*)d_in[7];
    const float* kb    = (const float*)d_in[8];
    const float* vw    = (const float*)d_in[9];
    const float* vb    = (const float*)d_in[10];
    const float* sw    = (const float*)d_in[11];
    const float* sb    = (const float*)d_in[12];
    float* out = (float*)d_out;

    k_setup<<<16, 256>>>(X, lin_w, lin_b, gam, bet, kw, kb, vw, vb, px, py, sw,
                         out + M_OFF);
    k_tab2<<<112, 256>>>();
    k_tab3<<<5568, 256>>>(sb);
    k_main<<<dim3(6, 64, 8), dim3(24, 16)>>>(px, py, out);
}

// round 14
// speedup vs baseline: 1.5007x; 1.5007x over previous
#include <cuda_runtime.h>

// Shapes (fixed): h=8, n=8, d=512, c=64, c2=32, i=96, kk=3
// Output layout: [ T (8*64*96*96) | M (8*8*32) | P (8*8*64*96*96) | w (same as P) ]
#define T_OFF   0
#define M_OFF   4718592
#define P_OFF   4720640
#define W_OFF   42469376
#define INV24   (1.0f/24.0f)

// ---------------- scratch (device globals; no allocation) ----------------
__device__ __align__(16) float g_M[2048];                       // [n][h][32]
__device__ __align__(16) float g_Ak[4096],  g_Av[4096];         // [n][h][64]
__device__ __align__(16) float g_Bxk[49152], g_Byk[49152];      // [h][64][96]
__device__ __align__(16) float g_Bxv[49152], g_Byv[49152];      // [h][64][96]
__device__ __align__(16) float g_swX[36864], g_swY[36864];      // [slab][cin][o] (transposed)
__device__ __align__(16) float g_U[36864];                      // [n][h][o][s]
__device__ __align__(16) float g_Vx[442368], g_Vy[442368];      // [h][o][s][96]
__device__ __align__(16) float g_EX[147456];                    // [h][o][yc][96]
__device__ __align__(16) float g_EY[1179648];                   // [n][h][o][xc][96]
__device__ __align__(16) float g_VY[393216];                    // [n][h][o][96]

// ---- K1 (fused): per-head [embed -> axes -> btab] (b<8) | swtab (8..15) ----
__global__ void k_setup(const float* __restrict__ X, const float* __restrict__ lw,
                        const float* __restrict__ lb, const float* __restrict__ gam,
                        const float* __restrict__ bet,
                        const float* __restrict__ kw, const float* __restrict__ kb,
                        const float* __restrict__ vw, const float* __restrict__ vb,
                        const float* __restrict__ px, const float* __restrict__ py,
                        const float* __restrict__ sw, float* __restrict__ outM) {
    int b = blockIdx.x, t = threadIdx.x;
    if (b >= 8) {
        // ---- swtab: border-class conv weight tables, TRANSPOSED [slab][cin][o] ----
        #pragma unroll
        for (int k = 0; k < 2; k++) {
            int tt = (b - 8) * 512 + k * 256 + t;   // tt = o*64 + cin
            int o = tt >> 6, cin = tt & 63;
            int tr = cin * 64 + o;
            float s[3][3];
            const float* p = sw + tt * 9;
            #pragma unroll
            for (int ky = 0; ky < 3; ky++)
                #pragma unroll
                for (int kx = 0; kx < 3; kx++) s[ky][kx] = p[ky * 3 + kx];
            #pragma unroll
            for (int xc = 0; xc < 3; xc++)
                #pragma unroll
                for (int ky = 0; ky < 3; ky++) {
                    float v = (xc == 0) ? (s[ky][1] + s[ky][2])
                            : (xc == 1) ? (s[ky][0] + s[ky][1] + s[ky][2])
                                        : (s[ky][0] + s[ky][1]);
                    g_swX[(xc * 3 + ky) * 4096 + tr] = v;
                }
            #pragma unroll
            for (int yc = 0; yc < 3; yc++)
                #pragma unroll
                for (int kx = 0; kx < 3; kx++) {
                    float v = (yc == 0) ? (s[1][kx] + s[2][kx])
                            : (yc == 1) ? (s[0][kx] + s[1][kx] + s[2][kx])
                                        : (s[0][kx] + s[1][kx]);
                    g_swY[(yc * 3 + kx) * 4096 + tr] = v;
                }
        }
        return;
    }
    int h = b;
    __shared__ float Xs[4096];
    __shared__ float ys[256];
    __shared__ float Ms[256];     // M[n][c] for this head
    __shared__ float mu_s[32], iv_s[32];
    const float* Xh = X + h * 4096;
    for (int k = t; k < 4096; k += 256) Xs[k] = Xh[k];
    __syncthreads();

    // ---- linear (float4 weight loads, per-thread row) ----
    int nn = t >> 5, cc = t & 31;
    const float4* wr = (const float4*)(lw + (h * 32 + cc) * 512);
    const float4* xr = (const float4*)(Xs + nn * 512);
    float acc = 0.f;
    #pragma unroll 8
    for (int d = 0; d < 128; d++) {
        float4 a = xr[d], w = wr[d];
        acc += a.x * w.x + a.y * w.y + a.z * w.z + a.w * w.w;
    }
    acc += lb[h * 32 + cc];
    ys[t] = acc;
    __syncthreads();
    if (t < 32) {
        float m = 0.f;
        for (int j = 0; j < 8; j++) m += ys[j * 32 + t];
        m *= 0.125f;
        float v = 0.f;
        for (int j = 0; j < 8; j++) { float d0 = ys[j * 32 + t] - m; v += d0 * d0; }
        v *= 0.125f;
        mu_s[t] = m;
        iv_s[t] = rsqrtf(v + 1e-5f);
    }
    __syncthreads();
    float val = (acc - mu_s[cc]) * iv_s[cc] * gam[h * 32 + cc] + bet[h * 32 + cc];
    val = fmaxf(val, 0.f);
    Ms[t] = val;
    int midx = (nn * 8 + h) * 32 + cc;
    g_M[midx]  = val;
    outM[midx] = val;
    __syncthreads();

    // ---- axes: A_k/A_v (512 items: n x d) ----
    for (int k = t; k < 512; k += 256) {
        int d = k & 63, n2 = k >> 6;
        const float* kwr = kw + (h * 64 + d) * 64;
        const float* vwr = vw + (h * 64 + d) * 64;
        const float* Mr  = Ms + n2 * 32;
        float ak = 0.f, av = 0.f;
        #pragma unroll 8
        for (int c = 0; c < 32; c++) {
            float m = Mr[c];
            ak += (kwr[c] + kwr[c + 32]) * m;
            av += (vwr[c] + vwr[c + 32]) * m;
        }
        g_Ak[(n2 * 8 + h) * 64 + d] = ak + kb[h * 64 + d];
        g_Av[(n2 * 8 + h) * 64 + d] = av + vb[h * 64 + d];
    }

    // ---- btab: Bx/By tables (6144 items: d x pos) ----
    for (int k = t; k < 6144; k += 256) {
        int pos = k % 96, d = k / 96;
        const float* kwr = kw + (h * 64 + d) * 64;
        const float* vwr = vw + (h * 64 + d) * 64;
        float bxk = 0.f, byk = 0.f, bxv = 0.f, byv = 0.f;
        #pragma unroll 8
        for (int c = 0; c < 32; c++) {
            float pxv = px[c * 96 + pos];
            float pyv = py[c * 96 + pos];
            bxk += kwr[c]      * pxv;
            byk += kwr[c + 32] * pyv;
            bxv += vwr[c]      * pxv;
            byv += vwr[c + 32] * pyv;
        }
        int idx = (h * 64 + d) * 96 + pos;
        g_Bxk[idx] = bxk; g_Byk[idx] = byk; g_Bxv[idx] = bxv; g_Byv[idx] = byv;
    }
}

// ---- K2: smem-staged mini-GEMMs. 144 blocks = dir(2) x h(8) x s(9). -------
// dir 0: Vy[h,o,s,:] = swX[s,:,o] . Byk[h,:,:]   (+ U folded in)
// dir 1: Vx[h,o,s,:] = swY[s,:,o] . Bxk[h,:,:]
__global__ void __launch_bounds__(256) k_tab2() {
    int b = blockIdx.x;
    int dir = b / 72;
    int r = b % 72;
    int h = r / 9, s = r % 9;
    __shared__ float Bs[64 * 96];    // 24KB  B[c][pos]
    __shared__ float Wsm[64 * 64];   // 16KB  W[c][o]
    const float* B = dir ? (g_Bxk + h * 6144) : (g_Byk + h * 6144);
    const float* W = dir ? (g_swY + s * 4096) : (g_swX + s * 4096);
    float* Vout    = dir ? g_Vx : g_Vy;
    int t = threadIdx.x;
    for (int k = t; k < 6144; k += 256) Bs[k] = B[k];
    for (int k = t; k < 4096; k += 256) Wsm[k] = W[k];
    __syncthreads();

    int o  = t >> 2;        // 0..63
    int qg = t & 3;         // 0..3 ; quads q = qg + 4m, m = 0..5
    float4 acc[6];
    #pragma unroll
    for (int m = 0; m < 6; m++) acc[m] = make_float4(0.f, 0.f, 0.f, 0.f);
    for (int c = 0; c < 64; c++) {
        float w = Wsm[c * 64 + o];
        const float4* brow = (const float4*)(Bs + c * 96) + qg;
        #pragma unroll
        for (int m = 0; m < 6; m++) {
            float4 bv = brow[4 * m];
            acc[m].x += w * bv.x; acc[m].y += w * bv.y;
            acc[m].z += w * bv.z; acc[m].w += w * bv.w;
        }
    }
    float4* vo = (float4*)(Vout + ((h * 64 + o) * 9 + s) * 96) + qg;
    #pragma unroll
    for (int m = 0; m < 6; m++) vo[4 * m] = acc[m];

    if (dir == 0) {
        // U[n,h,o,s] = sum_c swX[s,c,o] * Ak[n,h,c]  (512 items, 2/thread)
        #pragma unroll
        for (int k = 0; k < 2; k++) {
            int item = k * 256 + t;
            int oo = item & 63, n = item >> 6;
            const float* ap = g_Ak + (n * 8 + h) * 64;
            float u = 0.f;
            #pragma unroll 8
            for (int c = 0; c < 64; c++) u += Wsm[c * 64 + oo] * ap[c];
            g_U[((n * 8 + h) * 64 + oo) * 9 + s] = u;
        }
    }
}

// --------- K3 (fused): ex (b<576) | ey (576..5183) | vy4 (5184..5567) ------
__global__ void k_tab3(const float* __restrict__ sb) {
    int b = blockIdx.x, tid = threadIdx.x;
    if (b < 576) {
        int t = b * 256 + tid;
        int jj = t % 96; int r = t / 96;
        int yc = r % 3;  r /= 3;
        int o = r % 64;  int h = r / 64;
        int base = ((h * 64 + o) * 3 + yc) * 3 * 96;
        float acc = 0.f;
        #pragma unroll
        for (int kx = 0; kx < 3; kx++) {
            int j2 = jj + kx - 1;
            if (j2 >= 0 && j2 < 96) acc += g_Vx[base + kx * 96 + j2];
        }
        g_EX[t] = expf(acc * INV24);
    } else if (b < 5184) {
        int t = (b - 576) * 256 + tid;
        int ii = t % 96; int r = t / 96;
        int xc = r % 3;  r /= 3;
        int o = r % 64;  r /= 64;
        int h = r % 8;   int n = r / 8;
        int ub = (((n * 8 + h) * 64 + o) * 3 + xc) * 3;
        int vb = ((h * 64 + o) * 3 + xc) * 3 * 96;
        float acc = sb[o];
        #pragma unroll
        for (int ky = 0; ky < 3; ky++) {
            int i2 = ii + ky - 1;
            if (i2 >= 0 && i2 < 96) acc += g_U[ub + ky] + g_Vy[vb + ky * 96 + i2];
        }
        g_EY[t] = expf(acc * INV24);
    } else {
        int t = (b - 5184) * 256 + tid;
        int q = t % 24; int r = t / 24;
        int o = r % 64;  r /= 64;
        int h = r % 8;   int n = r / 8;
        float av = g_Av[(n * 8 + h) * 64 + o];
        float4 by = *(const float4*)(g_Byv + (h * 64 + o) * 96 + q * 4);
        float4 vout = {av + by.x, av + by.y, av + by.z, av + by.w};
        *(float4*)(g_VY + ((n * 8 + h) * 64 + o) * 96 + q * 4) = vout;
    }
}

// -------- K4: main — two-pass, low-register, float4 stores (T, w, P) -------
__global__ void __launch_bounds__(384, 3) k_main(const float* __restrict__ px,
                                                 const float* __restrict__ py,
                                                 float* __restrict__ out) {
    int jq  = threadIdx.x;                           // 0..23 -> 4 jj each
    int jj0 = jq * 4;
    int ii  = blockIdx.x * 16 + threadIdx.y;         // 0..95
    int o   = blockIdx.y;                            // 0..63
    int n   = blockIdx.z;                            // 0..7
    int yc  = (ii == 0) ? 0 : ((ii == 95) ? 2 : 1);
    int off0 = (jq == 0)  ? 0   : 96;
    int off3 = (jq == 23) ? 192 : 96;

    int eyB = (n * 512 + o) * 288 + ii;
    int exB = (o * 3 + yc) * 96 + jj0;
    int vyB = (n * 512 + o) * 96 + ii;
    int bxB = o * 96 + jj0;

    float s0 = 0.f, s1 = 0.f, s2 = 0.f, s3 = 0.f;
    float a0 = 0.f, a1 = 0.f, a2 = 0.f, a3 = 0.f;
    #pragma unroll
    for (int h = 0; h < 8; h++) {
        const float* ey = g_EY + eyB + h * 18432;
        float eyM = ey[96], ey0 = ey[off0], ey3 = ey[off3];
        float4 ex = *(const float4*)(g_EX + exB + h * 18432);
        float  vy = g_VY[vyB + h * 6144];
        float4 bx = *(const float4*)(g_Bxv + bxB + h * 6144);
        float e0 = ey0 * ex.x, e1 = eyM * ex.y, e2 = eyM * ex.z, e3 = ey3 * ex.w;
        s0 += e0; s1 += e1; s2 += e2; s3 += e3;
        a0 += e0 * (vy + bx.x); a1 += e1 * (vy + bx.y);
        a2 += e2 * (vy + bx.z); a3 += e3 * (vy + bx.w);
    }
    float i0 = __fdividef(1.f, s0), i1 = __fdividef(1.f, s1);
    float i2 = __fdividef(1.f, s2), i3 = __fdividef(1.f, s3);

    int p0 = ii * 96 + jj0;
    float4 t4 = {a0 * i0, a1 * i1, a2 * i2, a3 * i3};
    __stcs((float4*)(out + T_OFF + (n * 64 + o) * 9216 + p0), t4);

    float4 pAdd;
    if (o < 32) {
        pAdd = *(const float4*)(px + o * 96 + jj0);
    } else {
        float v = py[(o - 32) * 96 + ii];
        pAdd = make_float4(v, v, v, v);
    }
    int wB = W_OFF + (n * 512 + o) * 9216 + p0;
    int pB = P_OFF + (n * 512 + o) * 9216 + p0;
    int mB = n * 256 + (o & 31);

    #pragma unroll
    for (int h = 0; h < 8; h++) {
        const float* ey = g_EY + eyB + h * 18432;
        float eyM = ey[96], ey0 = ey[off0], ey3 = ey[off3];
        float4 ex = *(const float4*)(g_EX + exB + h * 18432);
        float4 w4 = {ey0 * ex.x * i0, eyM * ex.y * i1,
                     eyM * ex.z * i2, ey3 * ex.w * i3};
        __stcs((float4*)(out + wB + h * 589824), w4);
        float m = g_M[mB + h * 32];
        float4 p4 = {m + pAdd.x, m + pAdd.y, m + pAdd.z, m + pAdd.w};
        __stcs((float4*)(out + pB + h * 589824), p4);
    }
}

// ---------------- launch ----------------------------------------------------
extern "C" void kernel_launch(void* const* d_in, const int* in_sizes, int n_in,
                              void* d_out, int out_size) {
    const float* X     = (const float*)d_in[0];
    const float* lin_w = (const float*)d_in[1];
    const float* lin_b = (const float*)d_in[2];
    const float* gam   = (const float*)d_in[3];
    const float* bet   = (const float*)d_in[4];
    const float* px    = (const float*)d_in[5];
    const float* py    = (const float*)d_in[6];
    const float* kw    = (const float*)d_in[7];
    const float* kb    = (const float*)d_in[8];
    const float* vw    = (const float*)d_in[9];
    const float* vb    = (const float*)d_in[10];
    const float* sw    = (const float*)d_in[11];
    const float* sb    = (const float*)d_in[12];
    float* out = (float*)d_out;

    k_setup<<<16, 256>>>(X, lin_w, lin_b, gam, bet, kw, kb, vw, vb, px, py, sw,
                         out + M_OFF);
    k_tab2<<<144, 256>>>();
    k_tab3<<<5568, 256>>>(sb);
    k_main<<<dim3(6, 64, 8), dim3(24, 16)>>>(px, py, out);
}

// round 15
// speedup vs baseline: 1.6483x; 1.0984x over previous
#include <cuda_runtime.h>

// Shapes (fixed): h=8, n=8, d=512, c=64, c2=32, i=96, kk=3
// Output layout: [ T (8*64*96*96) | M (8*8*32) | P (8*8*64*96*96) | w (same as P) ]
#define T_OFF   0
#define M_OFF   4718592
#define P_OFF   4720640
#define W_OFF   42469376
#define INV24   (1.0f/24.0f)

// ---------------- scratch (device globals; no allocation) ----------------
__device__ __align__(16) float g_M[2048];                       // [n][h][32]
__device__ __align__(16) float g_Ak[4096],  g_Av[4096];         // [n][h][64]
__device__ __align__(16) float g_Bxk[49152], g_Byk[49152];      // [h][64][96]
__device__ __align__(16) float g_Bxv[49152], g_Byv[49152];      // [h][64][96]
__device__ __align__(16) float g_swX[36864], g_swY[36864];      // [slab][cin][o] (transposed)
__device__ __align__(16) float g_U[36864];                      // [n][h][o][s]
__device__ __align__(16) float g_Vx[442368], g_Vy[442368];      // [h][o][s][96]
__device__ __align__(16) float g_EX[147456];                    // [h][o][yc][96]
__device__ __align__(16) float g_EY[1179648];                   // [n][h][o][xc][96]
__device__ __align__(16) float g_VY[393216];                    // [n][h][o][96]

// ---- K1 (fused): per-head [embed -> axes -> btab] (b<8) | swtab (8..15) ----
// Phase-overlapped smem pool (35KB):
//   phase1: Xs   = pool[0..4096)      X[h] 8x512
//           ys   = pool[4096..4352)
//   phase2: Ksm  = pool[0..4160)      kw[h] padded stride 65
//           Vsm  = pool[4160..8320)   vw[h] padded stride 65
//   both:   mu   = pool[8320..8352)   iv = pool[8352..8384)
//           Ms   = pool[8576..8832)   M[n][c] for this head
__global__ void k_setup(const float* __restrict__ X, const float* __restrict__ lw,
                        const float* __restrict__ lb, const float* __restrict__ gam,
                        const float* __restrict__ bet,
                        const float* __restrict__ kw, const float* __restrict__ kb,
                        const float* __restrict__ vw, const float* __restrict__ vb,
                        const float* __restrict__ px, const float* __restrict__ py,
                        const float* __restrict__ sw, float* __restrict__ outM) {
    int b = blockIdx.x, t = threadIdx.x;
    if (b >= 8) {
        // ---- swtab: border-class conv weight tables, TRANSPOSED [slab][cin][o] ----
        #pragma unroll
        for (int k = 0; k < 2; k++) {
            int tt = (b - 8) * 512 + k * 256 + t;   // tt = o*64 + cin
            int o = tt >> 6, cin = tt & 63;
            int tr = cin * 64 + o;
            float s[3][3];
            const float* p = sw + tt * 9;
            #pragma unroll
            for (int ky = 0; ky < 3; ky++)
                #pragma unroll
                for (int kx = 0; kx < 3; kx++) s[ky][kx] = p[ky * 3 + kx];
            #pragma unroll
            for (int xc = 0; xc < 3; xc++)
                #pragma unroll
                for (int ky = 0; ky < 3; ky++) {
                    float v = (xc == 0) ? (s[ky][1] + s[ky][2])
                            : (xc == 1) ? (s[ky][0] + s[ky][1] + s[ky][2])
                                        : (s[ky][0] + s[ky][1]);
                    g_swX[(xc * 3 + ky) * 4096 + tr] = v;
                }
            #pragma unroll
            for (int yc = 0; yc < 3; yc++)
                #pragma unroll
                for (int kx = 0; kx < 3; kx++) {
                    float v = (yc == 0) ? (s[1][kx] + s[2][kx])
                            : (yc == 1) ? (s[0][kx] + s[1][kx] + s[2][kx])
                                        : (s[0][kx] + s[1][kx]);
                    g_swY[(yc * 3 + kx) * 4096 + tr] = v;
                }
        }
        return;
    }
    int h = b;
    __shared__ float pool[8832];
    float* Xs  = pool;          // phase1
    float* ys  = pool + 4096;   // phase1
    float* Ksm = pool;          // phase2 (stride 65)
    float* Vsm = pool + 4160;   // phase2 (stride 65)
    float* mu_s = pool + 8320;
    float* iv_s = pool + 8352;
    float* Ms   = pool + 8576;

    const float* Xh = X + h * 4096;
    for (int k = t; k < 4096; k += 256) Xs[k] = Xh[k];
    __syncthreads();

    // ---- linear (float4 weight loads, per-thread row) ----
    int nn = t >> 5, cc = t & 31;
    const float4* wr = (const float4*)(lw + (h * 32 + cc) * 512);
    const float4* xr = (const float4*)(Xs + nn * 512);
    float acc = 0.f;
    #pragma unroll 8
    for (int d = 0; d < 128; d++) {
        float4 a = xr[d], w = wr[d];
        acc += a.x * w.x + a.y * w.y + a.z * w.z + a.w * w.w;
    }
    acc += lb[h * 32 + cc];
    __syncthreads();           // Xs reads done before ys write aliases nothing; keep order safe
    ys[t] = acc;
    __syncthreads();
    if (t < 32) {
        float m = 0.f;
        for (int j = 0; j < 8; j++) m += ys[j * 32 + t];
        m *= 0.125f;
        float v = 0.f;
        for (int j = 0; j < 8; j++) { float d0 = ys[j * 32 + t] - m; v += d0 * d0; }
        v *= 0.125f;
        mu_s[t] = m;
        iv_s[t] = rsqrtf(v + 1e-5f);
    }
    __syncthreads();
    float val = (acc - mu_s[cc]) * iv_s[cc] * gam[h * 32 + cc] + bet[h * 32 + cc];
    val = fmaxf(val, 0.f);
    int midx = (nn * 8 + h) * 32 + cc;
    g_M[midx]  = val;
    outM[midx] = val;
    __syncthreads();           // everyone done with ys/Xs region
    Ms[t] = val;

    // ---- stage kw[h], vw[h] into padded smem (coalesced gld, conflict-free) --
    const float* kwh = kw + h * 4096;
    const float* vwh = vw + h * 4096;
    for (int k = t; k < 4096; k += 256) {
        int d = k >> 6, c = k & 63;
        Ksm[d * 65 + c] = kwh[k];
        Vsm[d * 65 + c] = vwh[k];
    }
    __syncthreads();

    // ---- axes: A_k/A_v (512 items: n x d), all smem ----
    for (int k = t; k < 512; k += 256) {
        int d = k & 63, n2 = k >> 6;
        const float* kr = Ksm + d * 65;
        const float* vr = Vsm + d * 65;
        const float* Mr = Ms + n2 * 32;
        float ak = 0.f, av = 0.f;
        #pragma unroll 8
        for (int c = 0; c < 32; c++) {
            float m = Mr[c];
            ak += (kr[c] + kr[c + 32]) * m;
            av += (vr[c] + vr[c + 32]) * m;
        }
        g_Ak[(n2 * 8 + h) * 64 + d] = ak + kb[h * 64 + d];
        g_Av[(n2 * 8 + h) * 64 + d] = av + vb[h * 64 + d];
    }

    // ---- btab: Bx/By tables (6144 items: d x pos), weights from smem ----
    for (int k = t; k < 6144; k += 256) {
        int pos = k % 96, d = k / 96;
        const float* kr = Ksm + d * 65;
        const float* vr = Vsm + d * 65;
        float bxk = 0.f, byk = 0.f, bxv = 0.f, byv = 0.f;
        #pragma unroll 8
        for (int c = 0; c < 32; c++) {
            float pxv = px[c * 96 + pos];   // coalesced, L1-hot
            float pyv = py[c * 96 + pos];
            bxk += kr[c]      * pxv;
            byk += kr[c + 32] * pyv;
            bxv += vr[c]      * pxv;
            byv += vr[c + 32] * pyv;
        }
        int idx = (h * 64 + d) * 96 + pos;
        g_Bxk[idx] = bxk; g_Byk[idx] = byk; g_Bxv[idx] = bxv; g_Byv[idx] = byv;
    }
}

// ---- K2: smem-staged mini-GEMMs. 144 blocks = dir(2) x h(8) x s(9). -------
// dir 0: Vy[h,o,s,:] = swX[s,:,o] . Byk[h,:,:]   (+ U folded in)
// dir 1: Vx[h,o,s,:] = swY[s,:,o] . Bxk[h,:,:]
__global__ void __launch_bounds__(256) k_tab2() {
    int b = blockIdx.x;
    int dir = b / 72;
    int r = b % 72;
    int h = r / 9, s = r % 9;
    __shared__ float Bs[64 * 96];    // 24KB  B[c][pos]
    __shared__ float Wsm[64 * 64];   // 16KB  W[c][o]
    const float* B = dir ? (g_Bxk + h * 6144) : (g_Byk + h * 6144);
    const float* W = dir ? (g_swY + s * 4096) : (g_swX + s * 4096);
    float* Vout    = dir ? g_Vx : g_Vy;
    int t = threadIdx.x;
    for (int k = t; k < 6144; k += 256) Bs[k] = B[k];
    for (int k = t; k < 4096; k += 256) Wsm[k] = W[k];
    __syncthreads();

    int o  = t >> 2;        // 0..63
    int qg = t & 3;         // 0..3 ; quads q = qg + 4m, m = 0..5
    float4 acc[6];
    #pragma unroll
    for (int m = 0; m < 6; m++) acc[m] = make_float4(0.f, 0.f, 0.f, 0.f);
    for (int c = 0; c < 64; c++) {
        float w = Wsm[c * 64 + o];
        const float4* brow = (const float4*)(Bs + c * 96) + qg;
        #pragma unroll
        for (int m = 0; m < 6; m++) {
            float4 bv = brow[4 * m];
            acc[m].x += w * bv.x; acc[m].y += w * bv.y;
            acc[m].z += w * bv.z; acc[m].w += w * bv.w;
        }
    }
    float4* vo = (float4*)(Vout + ((h * 64 + o) * 9 + s) * 96) + qg;
    #pragma unroll
    for (int m = 0; m < 6; m++) vo[4 * m] = acc[m];

    if (dir == 0) {
        // U[n,h,o,s] = sum_c swX[s,c,o] * Ak[n,h,c]  (512 items, 2/thread)
        #pragma unroll
        for (int k = 0; k < 2; k++) {
            int item = k * 256 + t;
            int oo = item & 63, n = item >> 6;
            const float* ap = g_Ak + (n * 8 + h) * 64;
            float u = 0.f;
            #pragma unroll 8
            for (int c = 0; c < 64; c++) u += Wsm[c * 64 + oo] * ap[c];
            g_U[((n * 8 + h) * 64 + oo) * 9 + s] = u;
        }
    }
}

// --------- K3 (fused): ex (b<576) | ey (576..5183) | vy4 (5184..5567) ------
__global__ void k_tab3(const float* __restrict__ sb) {
    int b = blockIdx.x, tid = threadIdx.x;
    if (b < 576) {
        int t = b * 256 + tid;
        int jj = t % 96; int r = t / 96;
        int yc = r % 3;  r /= 3;
        int o = r % 64;  int h = r / 64;
        int base = ((h * 64 + o) * 3 + yc) * 3 * 96;
        float acc = 0.f;
        #pragma unroll
        for (int kx = 0; kx < 3; kx++) {
            int j2 = jj + kx - 1;
            if (j2 >= 0 && j2 < 96) acc += g_Vx[base + kx * 96 + j2];
        }
        g_EX[t] = expf(acc * INV24);
    } else if (b < 5184) {
        int t = (b - 576) * 256 + tid;
        int ii = t % 96; int r = t / 96;
        int xc = r % 3;  r /= 3;
        int o = r % 64;  r /= 64;
        int h = r % 8;   int n = r / 8;
        int ub = (((n * 8 + h) * 64 + o) * 3 + xc) * 3;
        int vb = ((h * 64 + o) * 3 + xc) * 3 * 96;
        float acc = sb[o];
        #pragma unroll
        for (int ky = 0; ky < 3; ky++) {
            int i2 = ii + ky - 1;
            if (i2 >= 0 && i2 < 96) acc += g_U[ub + ky] + g_Vy[vb + ky * 96 + i2];
        }
        g_EY[t] = expf(acc * INV24);
    } else {
        int t = (b - 5184) * 256 + tid;
        int q = t % 24; int r = t / 24;
        int o = r % 64;  r /= 64;
        int h = r % 8;   int n = r / 8;
        float av = g_Av[(n * 8 + h) * 64 + o];
        float4 by = *(const float4*)(g_Byv + (h * 64 + o) * 96 + q * 4);
        float4 vout = {av + by.x, av + by.y, av + by.z, av + by.w};
        *(float4*)(g_VY + ((n * 8 + h) * 64 + o) * 96 + q * 4) = vout;
    }
}

// -------- K4: main — two-pass, low-register, float4 stores (T, w, P) -------
__global__ void __launch_bounds__(384, 3) k_main(const float* __restrict__ px,
                                                 const float* __restrict__ py,
                                                 float* __restrict__ out) {
    int jq  = threadIdx.x;                           // 0..23 -> 4 jj each
    int jj0 = jq * 4;
    int ii  = blockIdx.x * 16 + threadIdx.y;         // 0..95
    int o   = blockIdx.y;                            // 0..63
    int n   = blockIdx.z;                            // 0..7
    int yc  = (ii == 0) ? 0 : ((ii == 95) ? 2 : 1);
    int off0 = (jq == 0)  ? 0   : 96;
    int off3 = (jq == 23) ? 192 : 96;

    int eyB = (n * 512 + o) * 288 + ii;
    int exB = (o * 3 + yc) * 96 + jj0;
    int vyB = (n * 512 + o) * 96 + ii;
    int bxB = o * 96 + jj0;

    float s0 = 0.f, s1 = 0.f, s2 = 0.f, s3 = 0.f;
    float a0 = 0.f, a1 = 0.f, a2 = 0.f, a3 = 0.f;
    #pragma unroll
    for (int h = 0; h < 8; h++) {
        const float* ey = g_EY + eyB + h * 18432;
        float eyM = ey[96], ey0 = ey[off0], ey3 = ey[off3];
        float4 ex = *(const float4*)(g_EX + exB + h * 18432);
        float  vy = g_VY[vyB + h * 6144];
        float4 bx = *(const float4*)(g_Bxv + bxB + h * 6144);
        float e0 = ey0 * ex.x, e1 = eyM * ex.y, e2 = eyM * ex.z, e3 = ey3 * ex.w;
        s0 += e0; s1 += e1; s2 += e2; s3 += e3;
        a0 += e0 * (vy + bx.x); a1 += e1 * (vy + bx.y);
        a2 += e2 * (vy + bx.z); a3 += e3 * (vy + bx.w);
    }
    float i0 = __fdividef(1.f, s0), i1 = __fdividef(1.f, s1);
    float i2 = __fdividef(1.f, s2), i3 = __fdividef(1.f, s3);

    int p0 = ii * 96 + jj0;
    float4 t4 = {a0 * i0, a1 * i1, a2 * i2, a3 * i3};
    __stcs((float4*)(out + T_OFF + (n * 64 + o) * 9216 + p0), t4);

    float4 pAdd;
    if (o < 32) {
        pAdd = *(const float4*)(px + o * 96 + jj0);
    } else {
        float v = py[(o - 32) * 96 + ii];
        pAdd = make_float4(v, v, v, v);
    }
    int wB = W_OFF + (n * 512 + o) * 9216 + p0;
    int pB = P_OFF + (n * 512 + o) * 9216 + p0;
    int mB = n * 256 + (o & 31);

    #pragma unroll
    for (int h = 0; h < 8; h++) {
        const float* ey = g_EY + eyB + h * 18432;
        float eyM = ey[96], ey0 = ey[off0], ey3 = ey[off3];
        float4 ex = *(const float4*)(g_EX + exB + h * 18432);
        float4 w4 = {ey0 * ex.x * i0, eyM * ex.y * i1,
                     eyM * ex.z * i2, ey3 * ex.w * i3};
        __stcs((float4*)(out + wB + h * 589824), w4);
        float m = g_M[mB + h * 32];
        float4 p4 = {m + pAdd.x, m + pAdd.y, m + pAdd.z, m + pAdd.w};
        __stcs((float4*)(out + pB + h * 589824), p4);
    }
}

// ---------------- launch ----------------------------------------------------
extern "C" void kernel_launch(void* const* d_in, const int* in_sizes, int n_in,
                              void* d_out, int out_size) {
    const float* X     = (const float*)d_in[0];
    const float* lin_w = (const float*)d_in[1];
    const float* lin_b = (const float*)d_in[2];
    const float* gam   = (const float*)d_in[3];
    const float* bet   = (const float*)d_in[4];
    const float* px    = (const float*)d_in[5];
    const float* py    = (const float*)d_in[6];
    const float* kw    = (const float*)d_in[7];
    const float* kb    = (const float*)d_in[8];
    const float* vw    = (const float*)d_in[9];
    const float* vb    = (const float*)d_in[10];
    const float* sw    = (const float*)d_in[11];
    const float* sb    = (const float*)d_in[12];
    float* out = (float*)d_out;

    k_setup<<<16, 256>>>(X, lin_w, lin_b, gam, bet, kw, kb, vw, vb, px, py, sw,
                         out + M_OFF);
    k_tab2<<<144, 256>>>();
    k_tab3<<<5568, 256>>>(sb);
    k_main<<<dim3(6, 64, 8), dim3(24, 16)>>>(px, py, out);
}

// round 16
// speedup vs baseline: 2.6748x; 1.6227x over previous
#include <cuda_runtime.h>

// Shapes (fixed): h=8, n=8, d=512, c=64, c2=32, i=96, kk=3
// Output layout: [ T (8*64*96*96) | M (8*8*32) | P (8*8*64*96*96) | w (same as P) ]
#define T_OFF   0
#define M_OFF   4718592
#define P_OFF   4720640
#define W_OFF   42469376
#define INV24   (1.0f/24.0f)

// ---------------- scratch (device globals; no allocation) ----------------
__device__ __align__(16) float g_M[2048];                       // [n][h][32]
__device__ __align__(16) float g_Ak[4096],  g_Av[4096];         // [n][h][64]
__device__ __align__(16) float g_Bxk[49152], g_Byk[49152];      // [h][64][96]
__device__ __align__(16) float g_Bxv[49152], g_Byv[49152];      // [h][64][96]
__device__ __align__(16) float g_swX[36864], g_swY[36864];      // [slab][cin][o] (transposed)
__device__ __align__(16) float g_U[36864];                      // [n][h][o][s]
__device__ __align__(16) float g_Vx[442368], g_Vy[442368];      // [h][o][s][96]
__device__ __align__(16) float g_EX[147456];                    // [h][o][yc][96]
__device__ __align__(16) float g_EY[1179648];                   // [n][h][o][xc][96]
__device__ __align__(16) float g_VY[393216];                    // [n][h][o][96]

// ---- K1: embed. 64 blocks = (h, cgroup-of-4). Warp = one n, 4 dots. ------
__global__ void __launch_bounds__(256) k_embed(
        const float* __restrict__ X, const float* __restrict__ lw,
        const float* __restrict__ lb, const float* __restrict__ gam,
        const float* __restrict__ bet, float* __restrict__ outM) {
    int h = blockIdx.x >> 3, cg = blockIdx.x & 7, c0 = cg * 4;
    int w = threadIdx.x >> 5, l = threadIdx.x & 31;   // warp w = n
    __shared__ float ys[32];          // [n][k]
    __shared__ float mu[4], iv[4];

    const float* xr = X + (h * 8 + w) * 512;
    const float* w0 = lw + (h * 32 + c0) * 512;
    float a0 = 0.f, a1 = 0.f, a2 = 0.f, a3 = 0.f;
    #pragma unroll 4
    for (int j = 0; j < 16; j++) {
        float xv = xr[l + 32 * j];
        a0 += xv * w0[l + 32 * j];
        a1 += xv * w0[512 + l + 32 * j];
        a2 += xv * w0[1024 + l + 32 * j];
        a3 += xv * w0[1536 + l + 32 * j];
    }
    #pragma unroll
    for (int off = 16; off; off >>= 1) {
        a0 += __shfl_xor_sync(~0u, a0, off);
        a1 += __shfl_xor_sync(~0u, a1, off);
        a2 += __shfl_xor_sync(~0u, a2, off);
        a3 += __shfl_xor_sync(~0u, a3, off);
    }
    if (l == 0) {
        ys[w * 4 + 0] = a0 + lb[h * 32 + c0 + 0];
        ys[w * 4 + 1] = a1 + lb[h * 32 + c0 + 1];
        ys[w * 4 + 2] = a2 + lb[h * 32 + c0 + 2];
        ys[w * 4 + 3] = a3 + lb[h * 32 + c0 + 3];
    }
    __syncthreads();
    if (threadIdx.x < 4) {
        int k = threadIdx.x;
        float m = 0.f;
        #pragma unroll
        for (int n = 0; n < 8; n++) m += ys[n * 4 + k];
        m *= 0.125f;
        float v = 0.f;
        #pragma unroll
        for (int n = 0; n < 8; n++) { float d0 = ys[n * 4 + k] - m; v += d0 * d0; }
        v *= 0.125f;
        mu[k] = m;
        iv[k] = rsqrtf(v + 1e-5f);
    }
    __syncthreads();
    if (threadIdx.x < 32) {
        int n = threadIdx.x >> 2, k = threadIdx.x & 3, c = c0 + k;
        float val = (ys[threadIdx.x] - mu[k]) * iv[k] * gam[h * 32 + c] + bet[h * 32 + c];
        val = fmaxf(val, 0.f);
        int idx = (n * 8 + h) * 32 + c;
        g_M[idx]  = val;
        outM[idx] = val;
    }
}

// ---- K2 (fused): btab (b<192) | axes per-head (192..199) | swtab (200..207)
__global__ void k_tab1(const float* __restrict__ kw, const float* __restrict__ kb,
                       const float* __restrict__ vw, const float* __restrict__ vb,
                       const float* __restrict__ px, const float* __restrict__ py,
                       const float* __restrict__ sw) {
    int b = blockIdx.x, t = threadIdx.x;
    if (b < 192) {
        // ---- btab: 49152 items (h,d,pos). kw reads warp-broadcast, px coalesced.
        int k = b * 256 + t;
        int pos = k % 96;
        int hd  = k / 96;
        int d = hd & 63, h = hd >> 6;
        const float* kwr = kw + (h * 64 + d) * 64;
        const float* vwr = vw + (h * 64 + d) * 64;
        float bxk = 0.f, byk = 0.f, bxv = 0.f, byv = 0.f;
        #pragma unroll 8
        for (int c = 0; c < 32; c++) {
            float pxv = px[c * 96 + pos];
            float pyv = py[c * 96 + pos];
            bxk += kwr[c]      * pxv;
            byk += kwr[c + 32] * pyv;
            bxv += vwr[c]      * pxv;
            byv += vwr[c + 32] * pyv;
        }
        int idx = (h * 64 + d) * 96 + pos;
        g_Bxk[idx] = bxk; g_Byk[idx] = byk; g_Bxv[idx] = bxv; g_Byv[idx] = byv;
    } else if (b < 200) {
        // ---- axes: one block per head, padded smem staging of kw/vw ----
        int h = b - 192;
        __shared__ float Ks[4160], Vs[4160];   // stride 65, conflict-free
        const float* kwh = kw + h * 4096;
        const float* vwh = vw + h * 4096;
        for (int k = t; k < 4096; k += 256) {
            int d = k >> 6, c = k & 63;
            Ks[d * 65 + c] = kwh[k];
            Vs[d * 65 + c] = vwh[k];
        }
        __syncthreads();
        #pragma unroll
        for (int kk2 = 0; kk2 < 2; kk2++) {
            int item = kk2 * 256 + t;          // item = n*64 + d
            int d = item & 63, n2 = item >> 6;
            const float* kr = Ks + d * 65;
            const float* vr = Vs + d * 65;
            const float* Mr = g_M + (n2 * 8 + h) * 32;
            float ak = 0.f, av = 0.f;
            #pragma unroll 8
            for (int c = 0; c < 32; c++) {
                float m = Mr[c];
                ak += (kr[c] + kr[c + 32]) * m;
                av += (vr[c] + vr[c + 32]) * m;
            }
            g_Ak[(n2 * 8 + h) * 64 + d] = ak + kb[h * 64 + d];
            g_Av[(n2 * 8 + h) * 64 + d] = av + vb[h * 64 + d];
        }
    } else {
        // ---- swtab: TRANSPOSED [slab][cin][o] (4096 items, 8 blocks) ----
        #pragma unroll
        for (int k = 0; k < 2; k++) {
            int tt = (b - 200) * 512 + k * 256 + t;   // tt = o*64 + cin
            int o = tt >> 6, cin = tt & 63;
            int tr = cin * 64 + o;
            float s[3][3];
            const float* p = sw + tt * 9;
            #pragma unroll
            for (int ky = 0; ky < 3; ky++)
                #pragma unroll
                for (int kx = 0; kx < 3; kx++) s[ky][kx] = p[ky * 3 + kx];
            #pragma unroll
            for (int xc = 0; xc < 3; xc++)
                #pragma unroll
                for (int ky = 0; ky < 3; ky++) {
                    float v = (xc == 0) ? (s[ky][1] + s[ky][2])
                            : (xc == 1) ? (s[ky][0] + s[ky][1] + s[ky][2])
                                        : (s[ky][0] + s[ky][1]);
                    g_swX[(xc * 3 + ky) * 4096 + tr] = v;
                }
            #pragma unroll
            for (int yc = 0; yc < 3; yc++)
                #pragma unroll
                for (int kx = 0; kx < 3; kx++) {
                    float v = (yc == 0) ? (s[1][kx] + s[2][kx])
                            : (yc == 1) ? (s[0][kx] + s[1][kx] + s[2][kx])
                                        : (s[0][kx] + s[1][kx]);
                    g_swY[(yc * 3 + kx) * 4096 + tr] = v;
                }
        }
    }
}

// ---- K3: smem-staged mini-GEMMs. 144 blocks = dir(2) x h(8) x s(9). -------
__global__ void __launch_bounds__(256) k_tab2() {
    int b = blockIdx.x;
    int dir = b / 72;
    int r = b % 72;
    int h = r / 9, s = r % 9;
    __shared__ float Bs[64 * 96];    // 24KB  B[c][pos]
    __shared__ float Wsm[64 * 64];   // 16KB  W[c][o]
    const float* B = dir ? (g_Bxk + h * 6144) : (g_Byk + h * 6144);
    const float* W = dir ? (g_swY + s * 4096) : (g_swX + s * 4096);
    float* Vout    = dir ? g_Vx : g_Vy;
    int t = threadIdx.x;
    for (int k = t; k < 6144; k += 256) Bs[k] = B[k];
    for (int k = t; k < 4096; k += 256) Wsm[k] = W[k];
    __syncthreads();

    int o  = t >> 2;
    int qg = t & 3;
    float4 acc[6];
    #pragma unroll
    for (int m = 0; m < 6; m++) acc[m] = make_float4(0.f, 0.f, 0.f, 0.f);
    for (int c = 0; c < 64; c++) {
        float w = Wsm[c * 64 + o];
        const float4* brow = (const float4*)(Bs + c * 96) + qg;
        #pragma unroll
        for (int m = 0; m < 6; m++) {
            float4 bv = brow[4 * m];
            acc[m].x += w * bv.x; acc[m].y += w * bv.y;
            acc[m].z += w * bv.z; acc[m].w += w * bv.w;
        }
    }
    float4* vo = (float4*)(Vout + ((h * 64 + o) * 9 + s) * 96) + qg;
    #pragma unroll
    for (int m = 0; m < 6; m++) vo[4 * m] = acc[m];

    if (dir == 0) {
        #pragma unroll
        for (int k = 0; k < 2; k++) {
            int item = k * 256 + t;
            int oo = item & 63, n = item >> 6;
            const float* ap = g_Ak + (n * 8 + h) * 64;
            float u = 0.f;
            #pragma unroll 8
            for (int c = 0; c < 64; c++) u += Wsm[c * 64 + oo] * ap[c];
            g_U[((n * 8 + h) * 64 + oo) * 9 + s] = u;
        }
    }
}

// --------- K4 (fused): ex (b<576) | ey (576..5183) | vy4 (5184..5567) ------
__global__ void k_tab3(const float* __restrict__ sb) {
    int b = blockIdx.x, tid = threadIdx.x;
    if (b < 576) {
        int t = b * 256 + tid;
        int jj = t % 96; int r = t / 96;
        int yc = r % 3;  r /= 3;
        int o = r % 64;  int h = r / 64;
        int base = ((h * 64 + o) * 3 + yc) * 3 * 96;
        float acc = 0.f;
        #pragma unroll
        for (int kx = 0; kx < 3; kx++) {
            int j2 = jj + kx - 1;
            if (j2 >= 0 && j2 < 96) acc += g_Vx[base + kx * 96 + j2];
        }
        g_EX[t] = expf(acc * INV24);
    } else if (b < 5184) {
        int t = (b - 576) * 256 + tid;
        int ii = t % 96; int r = t / 96;
        int xc = r % 3;  r /= 3;
        int o = r % 64;  r /= 64;
        int h = r % 8;   int n = r / 8;
        int ub = (((n * 8 + h) * 64 + o) * 3 + xc) * 3;
        int vb = ((h * 64 + o) * 3 + xc) * 3 * 96;
        float acc = sb[o];
        #pragma unroll
        for (int ky = 0; ky < 3; ky++) {
            int i2 = ii + ky - 1;
            if (i2 >= 0 && i2 < 96) acc += g_U[ub + ky] + g_Vy[vb + ky * 96 + i2];
        }
        g_EY[t] = expf(acc * INV24);
    } else {
        int t = (b - 5184) * 256 + tid;
        int q = t % 24; int r = t / 24;
        int o = r % 64;  r /= 64;
        int h = r % 8;   int n = r / 8;
        float av = g_Av[(n * 8 + h) * 64 + o];
        float4 by = *(const float4*)(g_Byv + (h * 64 + o) * 96 + q * 4);
        float4 vout = {av + by.x, av + by.y, av + by.z, av + by.w};
        *(float4*)(g_VY + ((n * 8 + h) * 64 + o) * 96 + q * 4) = vout;
    }
}

// -------- K5: main — two-pass, low-register, float4 stores (T, w, P) -------
__global__ void __launch_bounds__(384, 3) k_main(const float* __restrict__ px,
                                                 const float* __restrict__ py,
                                                 float* __restrict__ out) {
    int jq  = threadIdx.x;
    int jj0 = jq * 4;
    int ii  = blockIdx.x * 16 + threadIdx.y;
    int o   = blockIdx.y;
    int n   = blockIdx.z;
    int yc  = (ii == 0) ? 0 : ((ii == 95) ? 2 : 1);
    int off0 = (jq == 0)  ? 0   : 96;
    int off3 = (jq == 23) ? 192 : 96;

    int eyB = (n * 512 + o) * 288 + ii;
    int exB = (o * 3 + yc) * 96 + jj0;
    int vyB = (n * 512 + o) * 96 + ii;
    int bxB = o * 96 + jj0;

    float s0 = 0.f, s1 = 0.f, s2 = 0.f, s3 = 0.f;
    float a0 = 0.f, a1 = 0.f, a2 = 0.f, a3 = 0.f;
    #pragma unroll
    for (int h = 0; h < 8; h++) {
        const float* ey = g_EY + eyB + h * 18432;
        float eyM = ey[96], ey0 = ey[off0], ey3 = ey[off3];
        float4 ex = *(const float4*)(g_EX + exB + h * 18432);
        float  vy = g_VY[vyB + h * 6144];
        float4 bx = *(const float4*)(g_Bxv + bxB + h * 6144);
        float e0 = ey0 * ex.x, e1 = eyM * ex.y, e2 = eyM * ex.z, e3 = ey3 * ex.w;
        s0 += e0; s1 += e1; s2 += e2; s3 += e3;
        a0 += e0 * (vy + bx.x); a1 += e1 * (vy + bx.y);
        a2 += e2 * (vy + bx.z); a3 += e3 * (vy + bx.w);
    }
    float i0 = __fdividef(1.f, s0), i1 = __fdividef(1.f, s1);
    float i2 = __fdividef(1.f, s2), i3 = __fdividef(1.f, s3);

    int p0 = ii * 96 + jj0;
    float4 t4 = {a0 * i0, a1 * i1, a2 * i2, a3 * i3};
    __stcs((float4*)(out + T_OFF + (n * 64 + o) * 9216 + p0), t4);

    float4 pAdd;
    if (o < 32) {
        pAdd = *(const float4*)(px + o * 96 + jj0);
    } else {
        float v = py[(o - 32) * 96 + ii];
        pAdd = make_float4(v, v, v, v);
    }
    int wB = W_OFF + (n * 512 + o) * 9216 + p0;
    int pB = P_OFF + (n * 512 + o) * 9216 + p0;
    int mB = n * 256 + (o & 31);

    #pragma unroll
    for (int h = 0; h < 8; h++) {
        const float* ey = g_EY + eyB + h * 18432;
        float eyM = ey[96], ey0 = ey[off0], ey3 = ey[off3];
        float4 ex = *(const float4*)(g_EX + exB + h * 18432);
        float4 w4 = {ey0 * ex.x * i0, eyM * ex.y * i1,
                     eyM * ex.z * i2, ey3 * ex.w * i3};
        __stcs((float4*)(out + wB + h * 589824), w4);
        float m = g_M[mB + h * 32];
        float4 p4 = {m + pAdd.x, m + pAdd.y, m + pAdd.z, m + pAdd.w};
        __stcs((float4*)(out + pB + h * 589824), p4);
    }
}

// ---------------- launch ----------------------------------------------------
extern "C" void kernel_launch(void* const* d_in, const int* in_sizes, int n_in,
                              void* d_out, int out_size) {
    const float* X     = (const float*)d_in[0];
    const float* lin_w = (const float*)d_in[1];
    const float* lin_b = (const float*)d_in[2];
    const float* gam   = (const float*)d_in[3];
    const float* bet   = (const float*)d_in[4];
    const float* px    = (const float*)d_in[5];
    const float* py    = (const float*)d_in[6];
    const float* kw    = (const float*)d_in[7];
    const float* kb    = (const float*)d_in[8];
    const float* vw    = (const float*)d_in[9];
    const float* vb    = (const float*)d_in[10];
    const float* sw    = (const float*)d_in[11];
    const float* sb    = (const float*)d_in[12];
    float* out = (float*)d_out;

    k_embed<<<64, 256>>>(X, lin_w, lin_b, gam, bet, out + M_OFF);
    k_tab1<<<208, 256>>>(kw, kb, vw, vb, px, py, sw);
    k_tab2<<<144, 256>>>();
    k_tab3<<<5568, 256>>>(sb);
    k_main<<<dim3(6, 64, 8), dim3(24, 16)>>>(px, py, out);
}

// round 17
// speedup vs baseline: 2.7162x; 1.0155x over previous
#include <cuda_runtime.h>

// Shapes (fixed): h=8, n=8, d=512, c=64, c2=32, i=96, kk=3
// Output layout: [ T (8*64*96*96) | M (8*8*32) | P (8*8*64*96*96) | w (same as P) ]
#define T_OFF   0
#define M_OFF   4718592
#define P_OFF   4720640
#define W_OFF   42469376
#define INV24   (1.0f/24.0f)

// ---------------- scratch (device globals; no allocation) ----------------
__device__ __align__(16) float g_M[2048];                       // [n][h][32]
__device__ __align__(16) float g_Ak[4096],  g_Av[4096];         // [n][h][64]
__device__ __align__(16) float g_Bxk[49152], g_Byk[49152];      // [h][64][96]
__device__ __align__(16) float g_Bxv[49152], g_Byv[49152];      // [h][64][96]
__device__ __align__(16) float g_swX[36864], g_swY[36864];      // [slab][cin][o] (transposed)
__device__ __align__(16) float g_U[36864];                      // [n][h][o][s]
__device__ __align__(16) float g_Vx[442368], g_Vy[442368];      // [h][o][s][96]
__device__ __align__(16) float g_EX[147456];                    // [h][o][yc][96]
__device__ __align__(16) float g_EY[1179648];                   // [n][h][o][xc][96]
__device__ __align__(16) float g_VY[393216];                    // [n][h][o][96]

// ---- K1 (fused): btab (b<192) | embed+axes per-head (192..199) | swtab ----
__global__ void k_tab1(const float* __restrict__ X, const float* __restrict__ lw,
                       const float* __restrict__ lb, const float* __restrict__ gam,
                       const float* __restrict__ bet,
                       const float* __restrict__ kw, const float* __restrict__ kb,
                       const float* __restrict__ vw, const float* __restrict__ vb,
                       const float* __restrict__ px, const float* __restrict__ py,
                       const float* __restrict__ sw, float* __restrict__ outM) {
    int b = blockIdx.x, t = threadIdx.x;
    __shared__ float pool[8896];   // embed+axes blocks only
    if (b < 192) {
        // ---- btab: 49152 items (h,d,pos). kw reads warp-broadcast, px coalesced.
        int k = b * 256 + t;
        int pos = k % 96;
        int hd  = k / 96;
        int d = hd & 63, h = hd >> 6;
        const float* kwr = kw + (h * 64 + d) * 64;
        const float* vwr = vw + (h * 64 + d) * 64;
        float bxk = 0.f, byk = 0.f, bxv = 0.f, byv = 0.f;
        #pragma unroll 8
        for (int c = 0; c < 32; c++) {
            float pxv = px[c * 96 + pos];
            float pyv = py[c * 96 + pos];
            bxk += kwr[c]      * pxv;
            byk += kwr[c + 32] * pyv;
            bxv += vwr[c]      * pxv;
            byv += vwr[c + 32] * pyv;
        }
        int idx = (h * 64 + d) * 96 + pos;
        g_Bxk[idx] = bxk; g_Byk[idx] = byk; g_Bxv[idx] = bxv; g_Byv[idx] = byv;
    } else if (b < 200) {
        // ---- embed + axes for one head ----
        int h = b - 192;
        float* Ks = pool;            // 4160 (stride 65)
        float* Vs = pool + 4160;     // 4160
        float* ys = pool + 8320;     // 256  [n][c]
        float* Ms = pool + 8576;     // 256  [n][c]
        float* mu = pool + 8832 - 64;        // reuse tail: mu/iv inside ys? no —
        // note: pool is 8896 floats: Ks0..4160, Vs..8320, ys..8576, Ms..8832, mu/iv..8896
        mu = pool + 8832;            // 32
        float* iv = pool + 8864;     // 32

        // embed: warp w = n, 8 c-groups of 4, warp-reduced coalesced dots
        int w = t >> 5, l = t & 31;
        const float* xr = X + (h * 8 + w) * 512;
        for (int cg = 0; cg < 8; cg++) {
            int c0 = cg * 4;
            const float* w0 = lw + (h * 32 + c0) * 512;
            float a0 = 0.f, a1 = 0.f, a2 = 0.f, a3 = 0.f;
            #pragma unroll 4
            for (int j = 0; j < 16; j++) {
                float xv = xr[l + 32 * j];
                a0 += xv * w0[l + 32 * j];
                a1 += xv * w0[512 + l + 32 * j];
                a2 += xv * w0[1024 + l + 32 * j];
                a3 += xv * w0[1536 + l + 32 * j];
            }
            #pragma unroll
            for (int off = 16; off; off >>= 1) {
                a0 += __shfl_xor_sync(~0u, a0, off);
                a1 += __shfl_xor_sync(~0u, a1, off);
                a2 += __shfl_xor_sync(~0u, a2, off);
                a3 += __shfl_xor_sync(~0u, a3, off);
            }
            if (l == 0) {
                ys[w * 32 + c0 + 0] = a0 + lb[h * 32 + c0 + 0];
                ys[w * 32 + c0 + 1] = a1 + lb[h * 32 + c0 + 1];
                ys[w * 32 + c0 + 2] = a2 + lb[h * 32 + c0 + 2];
                ys[w * 32 + c0 + 3] = a3 + lb[h * 32 + c0 + 3];
            }
        }
        __syncthreads();
        if (t < 32) {
            float m = 0.f;
            #pragma unroll
            for (int j = 0; j < 8; j++) m += ys[j * 32 + t];
            m *= 0.125f;
            float v = 0.f;
            #pragma unroll
            for (int j = 0; j < 8; j++) { float d0 = ys[j * 32 + t] - m; v += d0 * d0; }
            v *= 0.125f;
            mu[t] = m;
            iv[t] = rsqrtf(v + 1e-5f);
        }
        __syncthreads();
        {
            int nn = t >> 5, cc = t & 31;
            float val = (ys[t] - mu[cc]) * iv[cc] * gam[h * 32 + cc] + bet[h * 32 + cc];
            val = fmaxf(val, 0.f);
            Ms[t] = val;
            int midx = (nn * 8 + h) * 32 + cc;
            g_M[midx]  = val;
            outM[midx] = val;
        }
        // stage kw/vw padded
        const float* kwh = kw + h * 4096;
        const float* vwh = vw + h * 4096;
        for (int k = t; k < 4096; k += 256) {
            int d = k >> 6, c = k & 63;
            Ks[d * 65 + c] = kwh[k];
            Vs[d * 65 + c] = vwh[k];
        }
        __syncthreads();
        #pragma unroll
        for (int kk2 = 0; kk2 < 2; kk2++) {
            int item = kk2 * 256 + t;          // item = n*64 + d
            int d = item & 63, n2 = item >> 6;
            const float* kr = Ks + d * 65;
            const float* vr = Vs + d * 65;
            const float* Mr = Ms + n2 * 32;
            float ak = 0.f, av = 0.f;
            #pragma unroll 8
            for (int c = 0; c < 32; c++) {
                float m = Mr[c];
                ak += (kr[c] + kr[c + 32]) * m;
                av += (vr[c] + vr[c + 32]) * m;
            }
            g_Ak[(n2 * 8 + h) * 64 + d] = ak + kb[h * 64 + d];
            g_Av[(n2 * 8 + h) * 64 + d] = av + vb[h * 64 + d];
        }
    } else {
        // ---- swtab: TRANSPOSED [slab][cin][o] (4096 items, 8 blocks) ----
        #pragma unroll
        for (int k = 0; k < 2; k++) {
            int tt = (b - 200) * 512 + k * 256 + t;   // tt = o*64 + cin
            int o = tt >> 6, cin = tt & 63;
            int tr = cin * 64 + o;
            float s[3][3];
            const float* p = sw + tt * 9;
            #pragma unroll
            for (int ky = 0; ky < 3; ky++)
                #pragma unroll
                for (int kx = 0; kx < 3; kx++) s[ky][kx] = p[ky * 3 + kx];
            #pragma unroll
            for (int xc = 0; xc < 3; xc++)
                #pragma unroll
                for (int ky = 0; ky < 3; ky++) {
                    float v = (xc == 0) ? (s[ky][1] + s[ky][2])
                            : (xc == 1) ? (s[ky][0] + s[ky][1] + s[ky][2])
                                        : (s[ky][0] + s[ky][1]);
                    g_swX[(xc * 3 + ky) * 4096 + tr] = v;
                }
            #pragma unroll
            for (int yc = 0; yc < 3; yc++)
                #pragma unroll
                for (int kx = 0; kx < 3; kx++) {
                    float v = (yc == 0) ? (s[1][kx] + s[2][kx])
                            : (yc == 1) ? (s[0][kx] + s[1][kx] + s[2][kx])
                                        : (s[0][kx] + s[1][kx]);
                    g_swY[(yc * 3 + kx) * 4096 + tr] = v;
                }
        }
    }
}

// ---- K2: smem-staged mini-GEMMs. 144 blocks = dir(2) x h(8) x s(9). -------
__global__ void __launch_bounds__(256) k_tab2() {
    int b = blockIdx.x;
    int dir = b / 72;
    int r = b % 72;
    int h = r / 9, s = r % 9;
    __shared__ float Bs[64 * 96];
    __shared__ float Wsm[64 * 64];
    const float* B = dir ? (g_Bxk + h * 6144) : (g_Byk + h * 6144);
    const float* W = dir ? (g_swY + s * 4096) : (g_swX + s * 4096);
    float* Vout    = dir ? g_Vx : g_Vy;
    int t = threadIdx.x;
    for (int k = t; k < 6144; k += 256) Bs[k] = B[k];
    for (int k = t; k < 4096; k += 256) Wsm[k] = W[k];
    __syncthreads();

    int o  = t >> 2;
    int qg = t & 3;
    float4 acc[6];
    #pragma unroll
    for (int m = 0; m < 6; m++) acc[m] = make_float4(0.f, 0.f, 0.f, 0.f);
    for (int c = 0; c < 64; c++) {
        float w = Wsm[c * 64 + o];
        const float4* brow = (const float4*)(Bs + c * 96) + qg;
        #pragma unroll
        for (int m = 0; m < 6; m++) {
            float4 bv = brow[4 * m];
            acc[m].x += w * bv.x; acc[m].y += w * bv.y;
            acc[m].z += w * bv.z; acc[m].w += w * bv.w;
        }
    }
    float4* vo = (float4*)(Vout + ((h * 64 + o) * 9 + s) * 96) + qg;
    #pragma unroll
    for (int m = 0; m < 6; m++) vo[4 * m] = acc[m];

    if (dir == 0) {
        #pragma unroll
        for (int k = 0; k < 2; k++) {
            int item = k * 256 + t;
            int oo = item & 63, n = item >> 6;
            const float* ap = g_Ak + (n * 8 + h) * 64;
            float u = 0.f;
            #pragma unroll 8
            for (int c = 0; c < 64; c++) u += Wsm[c * 64 + oo] * ap[c];
            g_U[((n * 8 + h) * 64 + oo) * 9 + s] = u;
        }
    }
}

// --------- K3 (fused): ex (b<576) | ey (576..5183) | vy4 (5184..5567) ------
__global__ void k_tab3(const float* __restrict__ sb) {
    int b = blockIdx.x, tid = threadIdx.x;
    if (b < 576) {
        int t = b * 256 + tid;
        int jj = t % 96; int r = t / 96;
        int yc = r % 3;  r /= 3;
        int o = r % 64;  int h = r / 64;
        int base = ((h * 64 + o) * 3 + yc) * 3 * 96;
        float acc = 0.f;
        #pragma unroll
        for (int kx = 0; kx < 3; kx++) {
            int j2 = jj + kx - 1;
            if (j2 >= 0 && j2 < 96) acc += g_Vx[base + kx * 96 + j2];
        }
        g_EX[t] = expf(acc * INV24);
    } else if (b < 5184) {
        int t = (b - 576) * 256 + tid;
        int ii = t % 96; int r = t / 96;
        int xc = r % 3;  r /= 3;
        int o = r % 64;  r /= 64;
        int h = r % 8;   int n = r / 8;
        int ub = (((n * 8 + h) * 64 + o) * 3 + xc) * 3;
        int vb = ((h * 64 + o) * 3 + xc) * 3 * 96;
        float acc = sb[o];
        #pragma unroll
        for (int ky = 0; ky < 3; ky++) {
            int i2 = ii + ky - 1;
            if (i2 >= 0 && i2 < 96) acc += g_U[ub + ky] + g_Vy[vb + ky * 96 + i2];
        }
        g_EY[t] = expf(acc * INV24);
    } else {
        int t = (b - 5184) * 256 + tid;
        int q = t % 24; int r = t / 24;
        int o = r % 64;  r /= 64;
        int h = r % 8;   int n = r / 8;
        float av = g_Av[(n * 8 + h) * 64 + o];
        float4 by = *(const float4*)(g_Byv + (h * 64 + o) * 96 + q * 4);
        float4 vout = {av + by.x, av + by.y, av + by.z, av + by.w};
        *(float4*)(g_VY + ((n * 8 + h) * 64 + o) * 96 + q * 4) = vout;
    }
}

// -------- K4: main — smem-staged tables, two LDS passes, float4 stores -----
// smem layout (floats):
//   EYs [8][3][16]  = 384    (h, xc, ii-local)
//   EXc [8][96]     = 768    (yc=1 center row)
//   EXe [8][96]     = 768    (edge yc row: 0 for block0, 2 for block5)
//   VYs [8][16]     = 128
//   BXs [8][96]     = 768
__global__ void __launch_bounds__(384, 3) k_main(const float* __restrict__ px,
                                                 const float* __restrict__ py,
                                                 float* __restrict__ out) {
    __shared__ float EYs[384], EXc[768], EXe[768], VYs[128], BXs[768];
    int jq  = threadIdx.x;                 // 0..23
    int jj0 = jq * 4;
    int iiL = threadIdx.y;                 // 0..15
    int bx  = blockIdx.x;
    int ii0 = bx * 16;
    int ii  = ii0 + iiL;
    int o   = blockIdx.y;
    int n   = blockIdx.z;
    int t   = threadIdx.y * 24 + threadIdx.x;   // 0..383

    // ---- stage tables (coalesced float4 LDG) ----
    {
        const float* eyBase = g_EY + (n * 512 + o) * 288;     // + h*18432
        // EYs: 96 float4
        if (t < 96) {
            int h = t / 12, rem = t % 12, xc = rem >> 2, k4 = rem & 3;
            *(float4*)(EYs + h * 48 + xc * 16 + k4 * 4) =
                *(const float4*)(eyBase + h * 18432 + xc * 96 + ii0 + k4 * 4);
        }
        // VYs: 32 float4  (threads 96..127)
        else if (t < 128) {
            int u = t - 96;
            int h = u >> 2, k4 = u & 3;
            *(float4*)(VYs + h * 16 + k4 * 4) =
                *(const float4*)(g_VY + (n * 512 + o) * 96 + h * 6144 + ii0 + k4 * 4);
        }
        // BXs: 192 float4 (threads 128..319)
        else if (t < 320) {
            int u = t - 128;
            int h = u / 24, j4 = u % 24;
            *(float4*)(BXs + h * 96 + j4 * 4) =
                *(const float4*)(g_Bxv + o * 96 + h * 6144 + j4 * 4);
        }
        // EXc yc=1: 192 float4 (all threads loop below)
        int ycE = (bx == 0) ? 0 : ((bx == 5) ? 2 : 1);
        const float* exBase = g_EX + o * 288;                 // + h*18432 + yc*96
        for (int u = t; u < 192; u += 384) {
            int h = u / 24, j4 = u % 24;
            *(float4*)(EXc + h * 96 + j4 * 4) =
                *(const float4*)(exBase + h * 18432 + 96 + j4 * 4);
        }
        for (int u = t; u < 192; u += 384) {
            int h = u / 24, j4 = u % 24;
            *(float4*)(EXe + h * 96 + j4 * 4) =
                *(const float4*)(exBase + h * 18432 + ycE * 96 + j4 * 4);
        }
    }
    __syncthreads();

    int o0 = (jq == 0)  ? 0  : 16;      // xc slot for element 0
    int o3 = (jq == 23) ? 32 : 16;      // xc slot for element 3
    const float* exRow = (ii == 0 || ii == 95) ? EXe : EXc;

    // ---- pass 1: sums ----
    float s0 = 0.f, s1 = 0.f, s2 = 0.f, s3 = 0.f;
    float a0 = 0.f, a1 = 0.f, a2 = 0.f, a3 = 0.f;
    #pragma unroll
    for (int h = 0; h < 8; h++) {
        const float* eyh = EYs + h * 48 + iiL;
        float eyM = eyh[16], ey0 = eyh[o0], ey3 = eyh[o3];
        float4 ex = *(const float4*)(exRow + h * 96 + jj0);
        float  vy = VYs[h * 16 + iiL];
        float4 bx4 = *(const float4*)(BXs + h * 96 + jj0);
        float e0 = ey0 * ex.x, e1 = eyM * ex.y, e2 = eyM * ex.z, e3 = ey3 * ex.w;
        s0 += e0; s1 += e1; s2 += e2; s3 += e3;
        a0 += e0 * (vy + bx4.x); a1 += e1 * (vy + bx4.y);
        a2 += e2 * (vy + bx4.z); a3 += e3 * (vy + bx4.w);
    }
    float i0 = __fdividef(1.f, s0), i1 = __fdividef(1.f, s1);
    float i2 = __fdividef(1.f, s2), i3 = __fdividef(1.f, s3);

    int p0 = ii * 96 + jj0;
    float4 t4 = {a0 * i0, a1 * i1, a2 * i2, a3 * i3};
    __stcs((float4*)(out + T_OFF + (n * 64 + o) * 9216 + p0), t4);

    float4 pAdd;
    if (o < 32) {
        pAdd = *(const float4*)(px + o * 96 + jj0);
    } else {
        float v = py[(o - 32) * 96 + ii];
        pAdd = make_float4(v, v, v, v);
    }
    int wB = W_OFF + (n * 512 + o) * 9216 + p0;
    int pB = P_OFF + (n * 512 + o) * 9216 + p0;
    int mB = n * 256 + (o & 31);

    // ---- pass 2: recompute e from smem, write w and P ----
    #pragma unroll
    for (int h = 0; h < 8; h++) {
        const float* eyh = EYs + h * 48 + iiL;
        float eyM = eyh[16], ey0 = eyh[o0], ey3 = eyh[o3];
        float4 ex = *(const float4*)(exRow + h * 96 + jj0);
        float4 w4 = {ey0 * ex.x * i0, eyM * ex.y * i1,
                     eyM * ex.z * i2, ey3 * ex.w * i3};
        __stcs((float4*)(out + wB + h * 589824), w4);
        float m = g_M[mB + h * 32];
        float4 p4 = {m + pAdd.x, m + pAdd.y, m + pAdd.z, m + pAdd.w};
        __stcs((float4*)(out + pB + h * 589824), p4);
    }
}

// ---------------- launch ----------------------------------------------------
extern "C" void kernel_launch(void* const* d_in, const int* in_sizes, int n_in,
                              void* d_out, int out_size) {
    const float* X     = (const float*)d_in[0];
    const float* lin_w = (const float*)d_in[1];
    const float* lin_b = (const float*)d_in[2];
    const float* gam   = (const float*)d_in[3];
    const float* bet   = (const float*)d_in[4];
    const float* px    = (const float*)d_in[5];
    const float* py    = (const float*)d_in[6];
    const float* kw    = (const float*)d_in[7];
    const float* kb    = (const float*)d_in[8];
    const float* vw    = (const float*)d_in[9];
    const float* vb    = (const float*)d_in[10];
    const float* sw    = (const float*)d_in[11];
    const float* sb    = (const float*)d_in[12];
    float* out = (float*)d_out;

    k_tab1<<<208, 256>>>(X, lin_w, lin_b, gam, bet, kw, kb, vw, vb, px, py, sw,
                         out + M_OFF);
    k_tab2<<<144, 256>>>();
    k_tab3<<<5568, 256>>>(sb);
    k_main<<<dim3(6, 64, 8), dim3(24, 16)>>>(px, py, out);
}